// round 4
// baseline (speedup 1.0000x reference)
#include <cuda_runtime.h>
#include <math.h>

#define NB   2
#define NCLS 3
#define NA   3
#define DD   96
#define KK   128
#define EPSV 1e-4f
#define BETA_V (1.0f/9.0f)

// accumulators: 0=l_pos 1=l_neg 2=l_other 3=reg_loss 4=cnt_pos 5=cnt_neg 6=cnt_other 7=reg_w
__device__ double g_acc[8];

__global__ void zero_kernel() {
    int t = threadIdx.x;
    if (t < 8) g_acc[t] = 0.0;
}

__device__ __forceinline__ float sigmoidf_(float x) {
    return 1.0f / (1.0f + __expf(-x));
}

// ---------------- negative focal loss with 3x3x3 peak filter ----------------
// grid: ((b*9 + ch)*96 + z) blocks, 256 threads
__global__ __launch_bounds__(256) void neg_kernel(const float* __restrict__ logit,
                                                  const float* __restrict__ prob_gt) {
    const int bid = blockIdx.x;
    const int z   = bid % DD;
    const int bc  = bid / DD;
    const int ch  = bc % (NCLS * NA);
    const int b   = bc / (NCLS * NA);
    const int a   = ch % NA;

    const size_t plane = (size_t)DD * DD;
    const float* base = logit + ((size_t)(b * NCLS * NA + ch)) * DD * plane;

    __shared__ float zm[98 * 98];   // z-reduced max over {z-1,z,z+1}, with 1-elem halo
    const int tid = threadIdx.x;

    // fill z-reduced plane (halo = -inf outside volume)
    for (int i = tid; i < 98 * 98; i += 256) {
        int y = i / 98 - 1;
        int x = i % 98 - 1;
        float m = -INFINITY;
        if (y >= 0 && y < DD && x >= 0 && x < DD) {
            size_t off = (size_t)y * DD + x;
            m = base[(size_t)z * plane + off];
            if (z > 0)      m = fmaxf(m, base[(size_t)(z - 1) * plane + off]);
            if (z < DD - 1) m = fmaxf(m, base[(size_t)(z + 1) * plane + off]);
        }
        zm[i] = m;
    }
    __syncthreads();

    const float* pg_plane = prob_gt + ((size_t)(b * NA + a) * DD + z) * plane;
    const float* c_plane  = base + (size_t)z * plane;

    float lneg = 0.0f, cnt = 0.0f;
    for (int i = tid; i < DD * DD; i += 256) {
        int y = i / DD;
        int x = i % DD;
        int s = y * 98 + x;   // zm index of (y-1, x-1); center is s + 99
        float m = zm[s];
        m = fmaxf(m, zm[s + 1]);   m = fmaxf(m, zm[s + 2]);
        m = fmaxf(m, zm[s + 98]);  m = fmaxf(m, zm[s + 99]);  m = fmaxf(m, zm[s + 100]);
        m = fmaxf(m, zm[s + 196]); m = fmaxf(m, zm[s + 197]); m = fmaxf(m, zm[s + 198]);
        float c = c_plane[i];
        if (m == c) {                      // NMS peak — only then touch prob_gt / MUFU
            if (pg_plane[i] == -1.0f) {    // negative position
                float p = sigmoidf_(c);
                p = fminf(fmaxf(p, EPSV), 1.0f - EPSV);
                if (p > EPSV) {
                    float q = sigmoidf_(-c);               // stable 1-p
                    q = fminf(fmaxf(q, EPSV), 1.0f - EPSV);
                    lneg += -__logf(q) * p;                // w_neg = p (ALPHA=1)
                    cnt  += p;
                }
            }
        }
    }

    // block reduce (2 floats) -> double atomics
    for (int o = 16; o > 0; o >>= 1) {
        lneg += __shfl_down_sync(0xffffffffu, lneg, o);
        cnt  += __shfl_down_sync(0xffffffffu, cnt,  o);
    }
    __shared__ float red[8][2];
    int wid = tid >> 5, lid = tid & 31;
    if (lid == 0) { red[wid][0] = lneg; red[wid][1] = cnt; }
    __syncthreads();
    if (tid == 0) {
        float sl = 0.0f, sc = 0.0f;
        #pragma unroll
        for (int w = 0; w < 8; w++) { sl += red[w][0]; sc += red[w][1]; }
        atomicAdd(&g_acc[1], (double)sl);
        atomicAdd(&g_acc[5], (double)sc);
    }
}

// ---------------- positive / other-class / smooth-L1 (tiny) ----------------
// 1 block, 256 threads = B*K entries
__global__ __launch_bounds__(256) void pos_kernel(const float* __restrict__ logit,
                                                  const float* __restrict__ reg_pred,
                                                  const float* __restrict__ prob_gt,
                                                  const int*   __restrict__ coord_prob,
                                                  const int*   __restrict__ coord_diff,
                                                  const float* __restrict__ diff_gt,
                                                  const float* __restrict__ weight_cls) {
    const int t = threadIdx.x;
    const int b = t / KK;
    const int k = t % KK;
    const size_t plane = (size_t)DD * DD;
    const size_t vol   = (size_t)DD * plane;

    float lpos = 0.0f, cpos = 0.0f, loth = 0.0f, coth = 0.0f, rloss = 0.0f, rw = 0.0f;

    // ---- positive + other-class terms ----
    {
        const int* c = coord_prob + (size_t)(b * KK + k) * 4;
        int c0 = c[0], c1 = c[1], c2 = c[2], c3 = c[3];
        float mask = (c0 > -1) ? 1.0f : 0.0f;
        int a  = max(c0, 0), d = max(c1, 0), h = max(c2, 0), w = max(c3, 0);
        size_t sp = (size_t)d * plane + (size_t)h * DD + w;

        float po[NCLS];
        #pragma unroll
        for (int nc = 0; nc < NCLS; nc++) {
            float x = logit[((size_t)(b * NCLS * NA + nc * NA + a)) * vol + sp];
            float p = sigmoidf_(x);
            po[nc] = fminf(fmaxf(p, EPSV), 1.0f - EPSV);
        }
        float pg = prob_gt[((size_t)(b * NA + a)) * vol + sp];
        int cg = min(max((int)pg - 1, 0), NCLS - 1);
        float pt = po[cg];

        float wpos = (1.0f - pt) * weight_cls[cg] * mask;
        lpos += -logf(pt) * wpos;
        cpos += wpos;

        float gate_pt = (pt > 0.5f) ? 1.0f : 0.0f;
        float thr = pt - 0.1f;
        #pragma unroll
        for (int nc = 0; nc < NCLS; nc++) {
            if (nc == cg) continue;
            float gate_po = (po[nc] > 0.5f) ? 1.0f : 0.0f;
            float wo = fmaxf(po[nc] - thr, 0.0f) * gate_po * gate_pt * mask;
            loth += -logf(1.0f - po[nc]) * wo;
            coth += wo;
        }
    }

    // ---- smooth-L1 regression ----
    {
        const int* c = coord_diff + (size_t)(b * KK + k) * 4;
        int c0 = c[0], c1 = c[1], c2 = c[2], c3 = c[3];
        float maskd = (c0 > -1) ? 1.0f : 0.0f;
        int a  = max(c0, 0), d = max(c1, 0), h = max(c2, 0), w = max(c3, 0);
        size_t sp = (size_t)d * plane + (size_t)h * DD + w;
        const float* tg = diff_gt + (size_t)(b * KK + k) * 6;
        float s = 0.0f;
        #pragma unroll
        for (int j = 0; j < 6; j++) {
            float x = reg_pred[((size_t)(b * 6 * NA + j * NA + a)) * vol + sp];
            float n = fabsf(x - tg[j]);
            s += (n < BETA_V) ? (0.5f * n * n / BETA_V) : (n - 0.5f * BETA_V);
        }
        rloss += s * maskd;
        rw    += maskd;
    }

    // block reduce 6 floats
    for (int o = 16; o > 0; o >>= 1) {
        lpos  += __shfl_down_sync(0xffffffffu, lpos,  o);
        cpos  += __shfl_down_sync(0xffffffffu, cpos,  o);
        loth  += __shfl_down_sync(0xffffffffu, loth,  o);
        coth  += __shfl_down_sync(0xffffffffu, coth,  o);
        rloss += __shfl_down_sync(0xffffffffu, rloss, o);
        rw    += __shfl_down_sync(0xffffffffu, rw,    o);
    }
    __shared__ float red[8][6];
    int wid = t >> 5, lid = t & 31;
    if (lid == 0) {
        red[wid][0] = lpos; red[wid][1] = cpos; red[wid][2] = loth;
        red[wid][3] = coth; red[wid][4] = rloss; red[wid][5] = rw;
    }
    __syncthreads();
    if (t == 0) {
        float s[6] = {0, 0, 0, 0, 0, 0};
        #pragma unroll
        for (int w = 0; w < 8; w++)
            #pragma unroll
            for (int j = 0; j < 6; j++) s[j] += red[w][j];
        atomicAdd(&g_acc[0], (double)s[0]);
        atomicAdd(&g_acc[4], (double)s[1]);
        atomicAdd(&g_acc[2], (double)s[2]);
        atomicAdd(&g_acc[6], (double)s[3]);
        atomicAdd(&g_acc[3], (double)s[4]);
        atomicAdd(&g_acc[7], (double)s[5]);
    }
}

__global__ void fin_kernel(float* __restrict__ out) {
    if (threadIdx.x == 0) {
        double lp = g_acc[0], ln = g_acc[1], lo = g_acc[2], rl = g_acc[3];
        out[0] = (float)(lp + ln + lo + rl);   // LAMB1=LAMB2=LAMB3=1
        out[1] = (float)lp;
        out[2] = (float)ln;
        out[3] = (float)lo;
        out[4] = (float)rl;
        out[5] = (float)g_acc[4];
        out[6] = (float)g_acc[5];
        out[7] = (float)g_acc[6];
        out[8] = (float)g_acc[7];
    }
}

extern "C" void kernel_launch(void* const* d_in, const int* in_sizes, int n_in,
                              void* d_out, int out_size) {
    const float* cls_logit  = (const float*)d_in[0];
    const float* reg_pred   = (const float*)d_in[1];
    const float* prob_gt    = (const float*)d_in[2];
    const int*   coord_prob = (const int*)  d_in[3];
    const int*   coord_diff = (const int*)  d_in[4];
    const float* diff_gt    = (const float*)d_in[5];
    const float* weight_cls = (const float*)d_in[6];
    float* out = (float*)d_out;

    zero_kernel<<<1, 32>>>();
    neg_kernel<<<NB * NCLS * NA * DD, 256>>>(cls_logit, prob_gt);
    pos_kernel<<<1, 256>>>(cls_logit, reg_pred, prob_gt,
                           coord_prob, coord_diff, diff_gt, weight_cls);
    fin_kernel<<<1, 32>>>(out);
}

// round 7
// speedup vs baseline: 1.9956x; 1.9956x over previous
#include <cuda_runtime.h>
#include <math.h>

#define NB   2
#define NCLS 3
#define NA   3
#define DD   96
#define KK   128
#define EPSV 1e-4f
#define BETA_V (1.0f/9.0f)
#define ST   100     // zm row stride (floats), multiple of 4
#define NT   192     // neg_kernel threads: 24 x-groups * 8 y-strips

// accumulators: 0=l_pos 1=l_neg 2=l_other 3=reg_loss 4=cnt_pos 5=cnt_neg 6=cnt_other 7=reg_w
__device__ double g_acc[8];

__global__ void zero_kernel() {
    if (threadIdx.x < 8) g_acc[threadIdx.x] = 0.0;
}

__device__ __forceinline__ float sigmoidf_(float x) {
    return 1.0f / (1.0f + __expf(-x));
}

// ---------------- negative focal loss with 3x3x3 peak filter ----------------
// grid: ((b*9 + ch)*96 + z) blocks, 192 threads
// smem zm: z-reduced max plane with 1-halo, stored col = xx+1 so that the
// x-1..x+4 window lands on two aligned float4 loads.
__global__ __launch_bounds__(NT) void neg_kernel(const float* __restrict__ logit,
                                                 const float* __restrict__ prob_gt) {
    const int bid = blockIdx.x;
    const int z   = bid % DD;
    const int bc  = bid / DD;
    const int ch  = bc % (NCLS * NA);
    const int b   = bc / (NCLS * NA);
    const int a   = ch % NA;

    const size_t plane = (size_t)DD * DD;
    const float* base = logit + ((size_t)(b * NCLS * NA + ch)) * DD * plane;
    const int zlo = max(z - 1, 0), zhi = min(z + 1, DD - 1);
    const float* s0 = base + (size_t)zlo * plane;
    const float* s1 = base + (size_t)z   * plane;   // center slice = c values
    const float* s2 = base + (size_t)zhi * plane;
    const float* pgp = prob_gt + ((size_t)(b * NA + a) * DD + z) * plane;

    __shared__ __align__(16) float zm[98 * ST];
    const int t = threadIdx.x;

    // ---- halo init: rows 0,97 (cols 0..99) + rows 1..96 cols {0,97,98,99} ----
    for (int j = t; j < 584; j += NT) {
        int idx;
        if (j < 200) {
            int rr = (j < 100) ? 0 : 97;
            idx = rr * ST + (j % 100);
        } else {
            int jj = j - 200;
            int rr = 1 + (jj % 96);
            int cc = jj / 96;                       // 0..3
            int col = (cc == 0) ? 0 : (96 + cc);    // 0,97,98,99
            idx = rr * ST + col;
        }
        zm[idx] = -INFINITY;
    }

    // ---- interior z-reduction fill: 2304 float4 tasks, 12 per thread ----
    #pragma unroll
    for (int k = 0; k < 12; k++) {
        int tau = t + k * NT;
        int r   = 1 + tau / 24;          // stored row 1..96  (yy = r-1)
        int g   = tau - (r - 1) * 24;    // 0..23
        int xx0 = g * 4;
        size_t off = (size_t)(r - 1) * DD + xx0;
        float4 v0 = *(const float4*)(s0 + off);
        float4 v1 = *(const float4*)(s1 + off);
        float4 v2 = *(const float4*)(s2 + off);
        float m0 = fmaxf(fmaxf(v0.x, v1.x), v2.x);
        float m1 = fmaxf(fmaxf(v0.y, v1.y), v2.y);
        float m2 = fmaxf(fmaxf(v0.z, v1.z), v2.z);
        float m3 = fmaxf(fmaxf(v0.w, v1.w), v2.w);
        int p = r * ST + xx0 + 1;        // +1: shifted layout
        zm[p] = m0; zm[p + 1] = m1; zm[p + 2] = m2; zm[p + 3] = m3;
    }
    __syncthreads();

    // ---- main loop: per-thread 4-wide x-group, 12-row y strip, rolling y-max ----
    const int g  = t % 24;
    const int x  = g * 4;                // output cols x..x+3
    const int y0 = (t / 24) * 12;        // output rows y0..y0+11
    const int q  = x >> 2;               // float4 col index within a row (row=25 f4)

    const float4* zp = (const float4*)zm;

    float lneg = 0.0f, cnt = 0.0f;

    // prologue: stored rows y0 (A) and y0+1 (B); need rows y..y+2 per output y
    float4 a0 = zp[y0 * 25 + q],       a1 = zp[y0 * 25 + q + 1];
    float4 b0 = zp[(y0 + 1) * 25 + q], b1 = zp[(y0 + 1) * 25 + q + 1];
    float pr0 = b0.x, pr1 = b0.y, pr2 = b0.z, pr3 = b0.w, pr4 = b1.x, pr5 = b1.y;
    float p0 = fmaxf(a0.x, pr0), p1 = fmaxf(a0.y, pr1), p2 = fmaxf(a0.z, pr2);
    float p3 = fmaxf(a0.w, pr3), p4 = fmaxf(a1.x, pr4), p5 = fmaxf(a1.y, pr5);

    #pragma unroll 6
    for (int yy = 0; yy < 12; yy++) {
        const int y = y0 + yy;
        float4 c0 = zp[(y + 2) * 25 + q], c1v = zp[(y + 2) * 25 + q + 1];
        float n0 = c0.x, n1 = c0.y, n2 = c0.z, n3 = c0.w, n4 = c1v.x, n5 = c1v.y;

        // vertical window max (rows y..y+2) via rolling pair
        float M0 = fmaxf(p0, n0), M1 = fmaxf(p1, n1), M2 = fmaxf(p2, n2);
        float M3 = fmaxf(p3, n3), M4 = fmaxf(p4, n4), M5 = fmaxf(p5, n5);
        p0 = fmaxf(pr0, n0); p1 = fmaxf(pr1, n1); p2 = fmaxf(pr2, n2);
        p3 = fmaxf(pr3, n3); p4 = fmaxf(pr4, n4); p5 = fmaxf(pr5, n5);
        pr0 = n0; pr1 = n1; pr2 = n2; pr3 = n3; pr4 = n4; pr5 = n5;

        // horizontal window max
        float h0 = fmaxf(fmaxf(M0, M1), M2);
        float h1 = fmaxf(fmaxf(M1, M2), M3);
        float h2 = fmaxf(fmaxf(M2, M3), M4);
        float h3 = fmaxf(fmaxf(M3, M4), M5);

        float4 cv = *(const float4*)(s1  + (size_t)y * DD + x);
        float4 pv = *(const float4*)(pgp + (size_t)y * DD + x);

        #define PROC_(hv, cvv, pvv)                                          \
            if (hv == cvv && pvv == -1.0f) {                                 \
                float pp = fminf(fmaxf(sigmoidf_(cvv), EPSV), 1.0f - EPSV);  \
                if (pp > EPSV) {                                             \
                    float qq = fminf(fmaxf(sigmoidf_(-cvv), EPSV), 1.0f - EPSV); \
                    lneg += -__logf(qq) * pp;                                \
                    cnt  += pp;                                              \
                }                                                            \
            }
        PROC_(h0, cv.x, pv.x)
        PROC_(h1, cv.y, pv.y)
        PROC_(h2, cv.z, pv.z)
        PROC_(h3, cv.w, pv.w)
        #undef PROC_
    }

    // ---- block reduce (6 warps) -> double atomics ----
    for (int o = 16; o > 0; o >>= 1) {
        lneg += __shfl_down_sync(0xffffffffu, lneg, o);
        cnt  += __shfl_down_sync(0xffffffffu, cnt,  o);
    }
    __shared__ float red[6][2];
    int wid = t >> 5, lid = t & 31;
    if (lid == 0) { red[wid][0] = lneg; red[wid][1] = cnt; }
    __syncthreads();
    if (t == 0) {
        float sl = 0.0f, sc = 0.0f;
        #pragma unroll
        for (int w = 0; w < 6; w++) { sl += red[w][0]; sc += red[w][1]; }
        atomicAdd(&g_acc[1], (double)sl);
        atomicAdd(&g_acc[5], (double)sc);
    }
}

// ---------------- positive / other-class / smooth-L1 (tiny) ----------------
__global__ __launch_bounds__(256) void pos_kernel(const float* __restrict__ logit,
                                                  const float* __restrict__ reg_pred,
                                                  const float* __restrict__ prob_gt,
                                                  const int*   __restrict__ coord_prob,
                                                  const int*   __restrict__ coord_diff,
                                                  const float* __restrict__ diff_gt,
                                                  const float* __restrict__ weight_cls) {
    const int t = threadIdx.x;
    const int b = t / KK;
    const int k = t % KK;
    const size_t plane = (size_t)DD * DD;
    const size_t vol   = (size_t)DD * plane;

    float lpos = 0.0f, cpos = 0.0f, loth = 0.0f, coth = 0.0f, rloss = 0.0f, rw = 0.0f;

    {
        const int* c = coord_prob + (size_t)(b * KK + k) * 4;
        int c0 = c[0], c1 = c[1], c2 = c[2], c3 = c[3];
        float mask = (c0 > -1) ? 1.0f : 0.0f;
        int a = max(c0, 0), d = max(c1, 0), h = max(c2, 0), w = max(c3, 0);
        size_t sp = (size_t)d * plane + (size_t)h * DD + w;

        float po[NCLS];
        #pragma unroll
        for (int nc = 0; nc < NCLS; nc++) {
            float x = logit[((size_t)(b * NCLS * NA + nc * NA + a)) * vol + sp];
            float p = sigmoidf_(x);
            po[nc] = fminf(fmaxf(p, EPSV), 1.0f - EPSV);
        }
        float pg = prob_gt[((size_t)(b * NA + a)) * vol + sp];
        int cg = min(max((int)pg - 1, 0), NCLS - 1);
        float pt = po[cg];

        float wpos = (1.0f - pt) * weight_cls[cg] * mask;
        lpos += -logf(pt) * wpos;
        cpos += wpos;

        float gate_pt = (pt > 0.5f) ? 1.0f : 0.0f;
        float thr = pt - 0.1f;
        #pragma unroll
        for (int nc = 0; nc < NCLS; nc++) {
            if (nc == cg) continue;
            float gate_po = (po[nc] > 0.5f) ? 1.0f : 0.0f;
            float wo = fmaxf(po[nc] - thr, 0.0f) * gate_po * gate_pt * mask;
            loth += -logf(1.0f - po[nc]) * wo;
            coth += wo;
        }
    }

    {
        const int* c = coord_diff + (size_t)(b * KK + k) * 4;
        int c0 = c[0], c1 = c[1], c2 = c[2], c3 = c[3];
        float maskd = (c0 > -1) ? 1.0f : 0.0f;
        int a = max(c0, 0), d = max(c1, 0), h = max(c2, 0), w = max(c3, 0);
        size_t sp = (size_t)d * plane + (size_t)h * DD + w;
        const float* tg = diff_gt + (size_t)(b * KK + k) * 6;
        float s = 0.0f;
        #pragma unroll
        for (int j = 0; j < 6; j++) {
            float x = reg_pred[((size_t)(b * 6 * NA + j * NA + a)) * vol + sp];
            float n = fabsf(x - tg[j]);
            s += (n < BETA_V) ? (0.5f * n * n / BETA_V) : (n - 0.5f * BETA_V);
        }
        rloss += s * maskd;
        rw    += maskd;
    }

    for (int o = 16; o > 0; o >>= 1) {
        lpos  += __shfl_down_sync(0xffffffffu, lpos,  o);
        cpos  += __shfl_down_sync(0xffffffffu, cpos,  o);
        loth  += __shfl_down_sync(0xffffffffu, loth,  o);
        coth  += __shfl_down_sync(0xffffffffu, coth,  o);
        rloss += __shfl_down_sync(0xffffffffu, rloss, o);
        rw    += __shfl_down_sync(0xffffffffu, rw,    o);
    }
    __shared__ float red[8][6];
    int wid = t >> 5, lid = t & 31;
    if (lid == 0) {
        red[wid][0] = lpos; red[wid][1] = cpos; red[wid][2] = loth;
        red[wid][3] = coth; red[wid][4] = rloss; red[wid][5] = rw;
    }
    __syncthreads();
    if (t == 0) {
        float s[6] = {0, 0, 0, 0, 0, 0};
        #pragma unroll
        for (int w = 0; w < 8; w++)
            #pragma unroll
            for (int j = 0; j < 6; j++) s[j] += red[w][j];
        atomicAdd(&g_acc[0], (double)s[0]);
        atomicAdd(&g_acc[4], (double)s[1]);
        atomicAdd(&g_acc[2], (double)s[2]);
        atomicAdd(&g_acc[6], (double)s[3]);
        atomicAdd(&g_acc[3], (double)s[4]);
        atomicAdd(&g_acc[7], (double)s[5]);
    }
}

__global__ void fin_kernel(float* __restrict__ out) {
    if (threadIdx.x == 0) {
        double lp = g_acc[0], ln = g_acc[1], lo = g_acc[2], rl = g_acc[3];
        out[0] = (float)(lp + ln + lo + rl);
        out[1] = (float)lp;
        out[2] = (float)ln;
        out[3] = (float)lo;
        out[4] = (float)rl;
        out[5] = (float)g_acc[4];
        out[6] = (float)g_acc[5];
        out[7] = (float)g_acc[6];
        out[8] = (float)g_acc[7];
    }
}

extern "C" void kernel_launch(void* const* d_in, const int* in_sizes, int n_in,
                              void* d_out, int out_size) {
    const float* cls_logit  = (const float*)d_in[0];
    const float* reg_pred   = (const float*)d_in[1];
    const float* prob_gt    = (const float*)d_in[2];
    const int*   coord_prob = (const int*)  d_in[3];
    const int*   coord_diff = (const int*)  d_in[4];
    const float* diff_gt    = (const float*)d_in[5];
    const float* weight_cls = (const float*)d_in[6];
    float* out = (float*)d_out;

    zero_kernel<<<1, 32>>>();
    neg_kernel<<<NB * NCLS * NA * DD, NT>>>(cls_logit, prob_gt);
    pos_kernel<<<1, 256>>>(cls_logit, reg_pred, prob_gt,
                           coord_prob, coord_diff, diff_gt, weight_cls);
    fin_kernel<<<1, 32>>>(out);
}